// round 16
// baseline (speedup 1.0000x reference)
#include <cuda_runtime.h>
#include <cuda_bf16.h>
#include <math_constants.h>
#include <cstdint>

// Problem constants
#define B_  16
#define T_  2048
#define C_  1024
#define D_  64

// Scratch (device globals: allocation-free).
// g_Q: row-major, tf32-pre-rounded, pre-scaled by log2(e)/sqrt(C).
// g_K/g_V: MMA B-fragment order per 64-key tile (see qkv epilogue).
__device__ float g_Q[B_ * T_ * D_];
__device__ float g_K[B_ * T_ * D_];
__device__ float g_V[B_ * T_ * D_];
// W (tf32 hi only) in MMA B-fragment order (see wsplit_kernel).
__device__ float2 g_Wfrag[3 * 128 * 8 * 32];
// Split-KV partials: up to 4 chunks per q-tile. No zeroing needed: the
// combiner reads only chunks c < nc(qt), all of which are written.
__device__ float g_Opart[4][B_ * T_ * D_];
__device__ float g_Lpart[4][B_ * T_];

// ---------------------------------------------------------------------------
// helpers
// ---------------------------------------------------------------------------
__device__ __forceinline__ unsigned f2tf32(float a) {
    unsigned r;
    asm("cvt.rna.tf32.f32 %0, %1;" : "=r"(r) : "f"(a));
    return r;
}
__device__ __forceinline__ float f2tf32f(float a) {
    return __uint_as_float(f2tf32(a));
}
__device__ __forceinline__ void mma_tf32(float* c, const unsigned* a,
                                         unsigned b0, unsigned b1) {
    asm volatile(
        "mma.sync.aligned.m16n8k8.row.col.f32.tf32.tf32.f32 "
        "{%0,%1,%2,%3}, {%4,%5,%6,%7}, {%8,%9}, {%0,%1,%2,%3};\n"
        : "+f"(c[0]), "+f"(c[1]), "+f"(c[2]), "+f"(c[3])
        : "r"(a[0]), "r"(a[1]), "r"(a[2]), "r"(a[3]), "r"(b0), "r"(b1));
}
__device__ __forceinline__ void cp_async16(uint32_t saddr, const void* gptr) {
    asm volatile("cp.async.cg.shared.global [%0], [%1], 16;\n"
                 :: "r"(saddr), "l"(gptr));
}
#define CP_COMMIT() asm volatile("cp.async.commit_group;\n" ::: "memory")
#define CP_WAIT0()  asm volatile("cp.async.wait_group 0;\n" ::: "memory")
__device__ __forceinline__ uint32_t s2u(const void* p) {
    return (uint32_t)__cvta_generic_to_shared(p);
}

// ---------------------------------------------------------------------------
// Kernel 0: round W to tf32, store in MMA B-fragment order (float2).
// ---------------------------------------------------------------------------
__global__ __launch_bounds__(256)
void wsplit_kernel(const float* __restrict__ Wq,
                   const float* __restrict__ Wk,
                   const float* __restrict__ Wv) {
    int i    = blockIdx.x * 256 + threadIdx.x;
    int mat  = i >> 15;
    int rem  = i & 32767;
    int ksg  = rem >> 8;
    int j    = (rem >> 5) & 7;
    int lane = rem & 31;
    int g    = lane >> 2;
    int tig  = lane & 3;
    const float* W = (mat == 0) ? Wq : (mat == 1) ? Wk : Wv;
    int n = 8 * j + g;
    float w0 = W[(size_t)(8 * ksg + tig) * D_ + n];
    float w1 = W[(size_t)(8 * ksg + tig + 4) * D_ + n];
    g_Wfrag[i] = make_float2(f2tf32f(w0), f2tf32f(w1));
}

// ---------------------------------------------------------------------------
// Kernel 1: QKV projection, single-pass tf32 (xhi*whi).
// grid = (3, 256), mat fastest (X L2 reuse). BM=128, 256 threads.
// cp.async double-buffered, ONE barrier per k-chunk.
// ---------------------------------------------------------------------------
#define PBM 128
#define PKC 32
#define QKV_SMEM_BYTES (9216 * 4 + 2048 * 8)

__global__ __launch_bounds__(256)
void qkv_mma_kernel(const float* __restrict__ x) {
    extern __shared__ float dsm[];
    float*  Xs  = dsm;                          // [2][128][36]
    float2* WfS = (float2*)(dsm + 9216);        // [2][1024]

    const int mat = blockIdx.x;
    const float2* __restrict__ Wfg = g_Wfrag + mat * 32768;

    const int m0   = blockIdx.y * PBM;
    const int tid  = threadIdx.x;
    const int w    = tid >> 5;
    const int lane = tid & 31;
    const int g    = lane >> 2;
    const int tig  = lane & 3;
    const int r0   = 16 * w + g;
    const int r1   = r0 + 8;

    const uint32_t xs_u = s2u(Xs);
    const uint32_t wf_u = s2u(WfS);

    auto issue_stage = [&](int s, int k0) {
#pragma unroll
        for (int it = 0; it < 4; it++) {
            int i  = tid + 256 * it;
            int r  = i >> 3;
            int c4 = i & 7;
            cp_async16(xs_u + (uint32_t)(s * 4608 + r * 36 + 4 * c4) * 4,
                       x + (size_t)(m0 + r) * C_ + k0 + 4 * c4);
        }
        const float4* src = reinterpret_cast<const float4*>(
            Wfg + (k0 >> 3) * 256);
#pragma unroll
        for (int it = 0; it < 2; it++) {
            int i = tid + 256 * it;
            cp_async16(wf_u + (uint32_t)(s * 8192 + i * 16), src + i);
        }
    };

    float acc[8][4];
#pragma unroll
    for (int j = 0; j < 8; j++)
#pragma unroll
        for (int e = 0; e < 4; e++) acc[j][e] = 0.0f;

    issue_stage(0, 0);
    CP_COMMIT();

    for (int it = 0; it < 32; it++) {
        const int s = it & 1;
        CP_WAIT0();                      // chunk `it` landed (flying since it-1)
        __syncthreads();                 // readers of buf s^1 done; buf s visible
        if (it + 1 < 32) {
            issue_stage(s ^ 1, PKC * (it + 1));
            CP_COMMIT();
        }

        const float*  Xb = Xs + s * 4608;
        const float2* Wb = WfS + s * 1024;
#pragma unroll
        for (int ks = 0; ks < 4; ks++) {
            const int kc = 8 * ks;
            unsigned ahi[4];
            ahi[0] = f2tf32(Xb[r0 * 36 + kc + tig]);
            ahi[1] = f2tf32(Xb[r1 * 36 + kc + tig]);
            ahi[2] = f2tf32(Xb[r0 * 36 + kc + tig + 4]);
            ahi[3] = f2tf32(Xb[r1 * 36 + kc + tig + 4]);
#pragma unroll
            for (int j = 0; j < 8; j++) {
                float2 wf = Wb[ks * 256 + j * 32 + lane];
                mma_tf32(acc[j], ahi,
                         __float_as_uint(wf.x), __float_as_uint(wf.y));
            }
        }
    }

    // ---- Epilogue ----
    if (mat == 0) {
        // Q: row-major, scaled by log2(e)/sqrt(C) (base-2 softmax), tf32-rounded
        const float sc = 1.4426950408889634f / 32.0f;
#pragma unroll
        for (int j = 0; j < 8; j++) {
            int c = 8 * j + 2 * tig;
            *reinterpret_cast<float2*>(&g_Q[(size_t)(m0 + r0) * D_ + c]) =
                make_float2(f2tf32f(acc[j][0] * sc), f2tf32f(acc[j][1] * sc));
            *reinterpret_cast<float2*>(&g_Q[(size_t)(m0 + r1) * D_ + c]) =
                make_float2(f2tf32f(acc[j][2] * sc), f2tf32f(acc[j][3] * sc));
        }
    } else if (mat == 1) {
        // K scatter into QK^T B-fragment order.
        const int tileG = (m0 >> 6) + (w >> 2);
        const int jn0   = 2 * (w & 3);
        const int jn1   = jn0 + 1;
        const int slot  = tig >> 1;
        const int tp0   = (2 * tig) & 3;
        const int tp1   = tp0 + 1;
#pragma unroll
        for (int j = 0; j < 8; j++) {
            size_t base = ((size_t)(tileG * 8 + j) * 8);
            size_t b0i  = ((base + jn0) * 32 + 4 * g) * 2 + slot;
            size_t b1i  = ((base + jn1) * 32 + 4 * g) * 2 + slot;
            g_K[b0i + 2 * tp0] = f2tf32f(acc[j][0]);
            g_K[b0i + 2 * tp1] = f2tf32f(acc[j][1]);
            g_K[b1i + 2 * tp0] = f2tf32f(acc[j][2]);
            g_K[b1i + 2 * tp1] = f2tf32f(acc[j][3]);
        }
    } else {
        // V scatter into PV B-fragment order.
        const int tileG = (m0 >> 6) + (w >> 2);
        const int rks0  = 2 * (w & 3);
        const int rks1  = rks0 + 1;
        const int slot  = g >> 2;
        const int tigv  = g & 3;
#pragma unroll
        for (int j = 0; j < 8; j++) {
            size_t base0 = ((size_t)(tileG * 8 + rks0) * 8 + j) * 64;
            size_t base1 = ((size_t)(tileG * 8 + rks1) * 8 + j) * 64;
            int gv0 = 2 * tig, gv1 = 2 * tig + 1;
            g_V[base0 + (4 * gv0 + tigv) * 2 + slot] = f2tf32f(acc[j][0]);
            g_V[base0 + (4 * gv1 + tigv) * 2 + slot] = f2tf32f(acc[j][1]);
            g_V[base1 + (4 * gv0 + tigv) * 2 + slot] = f2tf32f(acc[j][2]);
            g_V[base1 + (4 * gv1 + tigv) * 2 + slot] = f2tf32f(acc[j][3]);
        }
    }
}

// ---------------------------------------------------------------------------
// Kernel 2: split-KV partial causal attention. grid (80, 16), 128 threads.
// K AND V double-buffered, issued together as ONE commit group one tile
// ahead. Per tile: one wait_group 0 + ONE __syncthreads, zero mid-tile
// waits (P rows are warp-private in Ps).
// Dynamic smem (floats): K[2][4096] + V[2][4096] + Ps 64x68 = 20736 = 82.9 KB.
// ---------------------------------------------------------------------------
#define ATT_SMEM_BYTES (20736 * 4)

__global__ __launch_bounds__(128)
void attn_part_kernel() {
    extern __shared__ float dsm[];
    float2* Ksf = reinterpret_cast<float2*>(dsm);           // [2][2048] float2
    float2* Vsf = reinterpret_cast<float2*>(dsm + 8192);    // [2][2048] float2
    float*  Ps  = dsm + 16384;                              // [64][68]; Q staging

    // Map work id -> (qt, chunk), qt descending so heavy chunks launch first.
    int qt = 0, ch = 0;
    {
        int wid = blockIdx.x;
        int acc = 0;
#pragma unroll
        for (int q = 31; q >= 0; q--) {
            int nc = (q >> 3) + 1;
            if (wid < acc + nc) { qt = q; ch = wid - acc; break; }
            acc += nc;
        }
    }
    const int b   = blockIdx.y;
    const int q0  = qt * 64;
    const int jt0 = ch * 8;
    const int jt1 = min(jt0 + 8, qt + 1);

    const int tid  = threadIdx.x;
    const int lane = tid & 31;
    const int g    = lane >> 2;
    const int tig  = lane & 3;
    const int r0   = 16 * (tid >> 5) + g;
    const int r1   = r0 + 8;

    const uint32_t k_u = s2u(Ksf);
    const uint32_t v_u = s2u(Vsf);

    // Issue K(jt)+V(jt) into buffer s. Offsets in BYTES: buffer stride is
    // 1024 float4 = 16 KB; element i is the i-th float4 of the tile.
    auto issue_kv = [&](int s, int jt) {
        const float4* Kg = reinterpret_cast<const float4*>(g_K)
                         + (size_t)(b * (T_ / 64) + jt) * 1024;
        const float4* Vg = reinterpret_cast<const float4*>(g_V)
                         + (size_t)(b * (T_ / 64) + jt) * 1024;
#pragma unroll
        for (int it = 0; it < 8; it++) {
            int i = tid + 128 * it;
            cp_async16(k_u + (uint32_t)(s * 1024 + i) * 16, Kg + i);
            cp_async16(v_u + (uint32_t)(s * 1024 + i) * 16, Vg + i);
        }
    };

    // Prefetch first K+V tile pair, then stage Q through Ps
    issue_kv(0, jt0);
    CP_COMMIT();
    {
        const float* Qg = g_Q + ((size_t)b * T_ + q0) * D_;
#pragma unroll
        for (int it = 0; it < 8; it++) {
            int i  = tid + 128 * it;
            int r  = i >> 4;
            int c4 = i & 15;
            *reinterpret_cast<float4*>(&Ps[r * 68 + 4 * c4]) =
                *reinterpret_cast<const float4*>(&Qg[(size_t)r * D_ + 4 * c4]);
        }
    }
    __syncthreads();

    unsigned qf[8][4];
#pragma unroll
    for (int ks = 0; ks < 8; ks++) {
        const int kc = 8 * ks;
        qf[ks][0] = __float_as_uint(Ps[r0 * 68 + kc + tig]);
        qf[ks][1] = __float_as_uint(Ps[r1 * 68 + kc + tig]);
        qf[ks][2] = __float_as_uint(Ps[r0 * 68 + kc + tig + 4]);
        qf[ks][3] = __float_as_uint(Ps[r1 * 68 + kc + tig + 4]);
    }

    float oacc[8][4];
#pragma unroll
    for (int j = 0; j < 8; j++)
#pragma unroll
        for (int e = 0; e < 4; e++) oacc[j][e] = 0.0f;
    float lr[2] = {0.0f, 0.0f};

    for (int jt = jt0; jt < jt1; jt++) {
        const int s = (jt - jt0) & 1;

        CP_WAIT0();       // KV(jt) landed (committed one full tile ago)
        __syncthreads();  // tile jt-1 readers of buf s^1 done; KV(jt) visible

        if (jt + 1 < jt1) {
            issue_kv(s ^ 1, jt + 1);
            CP_COMMIT();
        }

        // S = Q @ K^T on K buffer s (buffer stride 2048 float2)
        const float2* Kt = Ksf + s * 2048;
        float sacc[8][4];
#pragma unroll
        for (int j = 0; j < 8; j++)
#pragma unroll
            for (int e = 0; e < 4; e++) sacc[j][e] = 0.0f;
#pragma unroll
        for (int ks = 0; ks < 8; ks++) {
#pragma unroll
            for (int j = 0; j < 8; j++) {
                float2 kf = Kt[(ks * 8 + j) * 32 + lane];
                mma_tf32(sacc[j], qf[ks],
                         __float_as_uint(kf.x), __float_as_uint(kf.y));
            }
        }

        // Causal mask on the diagonal tile only
        if (jt == qt) {
#pragma unroll
            for (int j = 0; j < 8; j++) {
                int c = 8 * j + 2 * tig;
                if (c     > r0) sacc[j][0] = -CUDART_INF_F;
                if (c + 1 > r0) sacc[j][1] = -CUDART_INF_F;
                if (c     > r1) sacc[j][2] = -CUDART_INF_F;
                if (c + 1 > r1) sacc[j][3] = -CUDART_INF_F;
            }
        }

        // Fixed-max base-2 softmax: p = exp2(s); row sums via 2 quad shfls.
#pragma unroll
        for (int r = 0; r < 2; r++) {
            const int e0 = 2 * r, e1 = 2 * r + 1;
            float sum = 0.0f;
#pragma unroll
            for (int j = 0; j < 8; j++) {
                float p0 = exp2f(sacc[j][e0]);
                float p1 = exp2f(sacc[j][e1]);
                sacc[j][e0] = p0;
                sacc[j][e1] = p1;
                sum += p0 + p1;
            }
            sum += __shfl_xor_sync(0xffffffffu, sum, 1);
            sum += __shfl_xor_sync(0xffffffffu, sum, 2);
            lr[r] += sum;
        }

        // Write P (rounded to tf32) to warp-private rows of Ps — no barrier
#pragma unroll
        for (int j = 0; j < 8; j++) {
            int c = 8 * j + 2 * tig;
            *reinterpret_cast<float2*>(&Ps[r0 * 68 + c]) =
                make_float2(f2tf32f(sacc[j][0]), f2tf32f(sacc[j][1]));
            *reinterpret_cast<float2*>(&Ps[r1 * 68 + c]) =
                make_float2(f2tf32f(sacc[j][2]), f2tf32f(sacc[j][3]));
        }

        // O += P @ V on V buffer s — NO mid-tile wait (V landed with K)
        const float2* Vt = Vsf + s * 2048;
#pragma unroll
        for (int ks = 0; ks < 8; ks++) {
            const int kc = 8 * ks;
            unsigned pa[4];
            pa[0] = __float_as_uint(Ps[r0 * 68 + kc + tig]);
            pa[1] = __float_as_uint(Ps[r1 * 68 + kc + tig]);
            pa[2] = __float_as_uint(Ps[r0 * 68 + kc + tig + 4]);
            pa[3] = __float_as_uint(Ps[r1 * 68 + kc + tig + 4]);
#pragma unroll
            for (int j = 0; j < 8; j++) {
                float2 vf = Vt[(ks * 8 + j) * 32 + lane];
                mma_tf32(oacc[j], pa,
                         __float_as_uint(vf.x), __float_as_uint(vf.y));
            }
        }
    }

    // Store unnormalized partial O and l for this chunk
    float* Op = g_Opart[ch] + ((size_t)b * T_ + q0) * D_;
#pragma unroll
    for (int j = 0; j < 8; j++) {
        int c = 8 * j + 2 * tig;
        *reinterpret_cast<float2*>(&Op[(size_t)r0 * D_ + c]) =
            make_float2(oacc[j][0], oacc[j][1]);
        *reinterpret_cast<float2*>(&Op[(size_t)r1 * D_ + c]) =
            make_float2(oacc[j][2], oacc[j][3]);
    }
    if (tig == 0) {
        g_Lpart[ch][(size_t)b * T_ + q0 + r0] = lr[0];
        g_Lpart[ch][(size_t)b * T_ + q0 + r1] = lr[1];
    }
}

// ---------------------------------------------------------------------------
// Kernel 3: combine partials and normalize. One thread per float4 of output.
// ---------------------------------------------------------------------------
__global__ __launch_bounds__(256)
void norm_kernel(float* __restrict__ out) {
    int idx = blockIdx.x * 256 + threadIdx.x;     // 0 .. 524287
    int d4  = idx & 15;
    int t   = (idx >> 4) & (T_ - 1);
    int b   = idx >> 15;
    int nc  = ((t >> 6) >> 3) + 1;                // chunks for this q-tile

    size_t row = (size_t)b * T_ + t;
    float4 o = make_float4(0.f, 0.f, 0.f, 0.f);
    float  l = 0.f;
#pragma unroll 4
    for (int c = 0; c < nc; c++) {
        float4 p = *reinterpret_cast<const float4*>(
            &g_Opart[c][row * D_ + 4 * d4]);
        o.x += p.x; o.y += p.y; o.z += p.z; o.w += p.w;
        l += g_Lpart[c][row];
    }
    float inv = 1.0f / l;
    *reinterpret_cast<float4*>(&out[row * D_ + 4 * d4]) =
        make_float4(o.x * inv, o.y * inv, o.z * inv, o.w * inv);
}

// ---------------------------------------------------------------------------
extern "C" void kernel_launch(void* const* d_in, const int* in_sizes, int n_in,
                              void* d_out, int out_size) {
    const float* x  = (const float*)d_in[0];
    const float* Wq = (const float*)d_in[1];
    const float* Wk = (const float*)d_in[2];
    const float* Wv = (const float*)d_in[3];
    float* out = (float*)d_out;

    cudaFuncSetAttribute(qkv_mma_kernel,
                         cudaFuncAttributeMaxDynamicSharedMemorySize,
                         QKV_SMEM_BYTES);
    cudaFuncSetAttribute(attn_part_kernel,
                         cudaFuncAttributeMaxDynamicSharedMemorySize,
                         ATT_SMEM_BYTES);

    wsplit_kernel<<<384, 256>>>(Wq, Wk, Wv);
    qkv_mma_kernel<<<dim3(3, (B_ * T_) / PBM), 256, QKV_SMEM_BYTES>>>(x);
    attn_part_kernel<<<dim3(80, B_), 128, ATT_SMEM_BYTES>>>();
    norm_kernel<<<(B_ * T_ * D_ / 4) / 256, 256>>>(out);
}

// round 17
// speedup vs baseline: 1.0171x; 1.0171x over previous
#include <cuda_runtime.h>
#include <cuda_bf16.h>
#include <math_constants.h>
#include <cstdint>

// Problem constants
#define B_  16
#define T_  2048
#define C_  1024
#define D_  64

// Scratch (device globals: allocation-free).
// g_Q: row-major, tf32-pre-rounded, pre-scaled by log2(e)/sqrt(C).
// g_K/g_V: MMA B-fragment order per 64-key tile (see qkv epilogue).
__device__ float g_Q[B_ * T_ * D_];
__device__ float g_K[B_ * T_ * D_];
__device__ float g_V[B_ * T_ * D_];
// W (tf32 hi only) in MMA B-fragment order (see wsplit_kernel).
__device__ float2 g_Wfrag[3 * 128 * 8 * 32];
// Split-KV partials: up to 4 chunks per q-tile. No zeroing needed: the
// combiner reads only chunks c < nc(qt), all of which are written.
__device__ float g_Opart[4][B_ * T_ * D_];
__device__ float g_Lpart[4][B_ * T_];

// ---------------------------------------------------------------------------
// helpers
// ---------------------------------------------------------------------------
__device__ __forceinline__ unsigned f2tf32(float a) {
    unsigned r;
    asm("cvt.rna.tf32.f32 %0, %1;" : "=r"(r) : "f"(a));
    return r;
}
__device__ __forceinline__ float f2tf32f(float a) {
    return __uint_as_float(f2tf32(a));
}
__device__ __forceinline__ void mma_tf32(float* c, const unsigned* a,
                                         unsigned b0, unsigned b1) {
    asm volatile(
        "mma.sync.aligned.m16n8k8.row.col.f32.tf32.tf32.f32 "
        "{%0,%1,%2,%3}, {%4,%5,%6,%7}, {%8,%9}, {%0,%1,%2,%3};\n"
        : "+f"(c[0]), "+f"(c[1]), "+f"(c[2]), "+f"(c[3])
        : "r"(a[0]), "r"(a[1]), "r"(a[2]), "r"(a[3]), "r"(b0), "r"(b1));
}
__device__ __forceinline__ void cp_async16(uint32_t saddr, const void* gptr) {
    asm volatile("cp.async.cg.shared.global [%0], [%1], 16;\n"
                 :: "r"(saddr), "l"(gptr));
}
#define CP_COMMIT() asm volatile("cp.async.commit_group;\n" ::: "memory")
#define CP_WAIT0()  asm volatile("cp.async.wait_group 0;\n" ::: "memory")
__device__ __forceinline__ uint32_t s2u(const void* p) {
    return (uint32_t)__cvta_generic_to_shared(p);
}

// ---------------------------------------------------------------------------
// Kernel 0: round W to tf32, store in MMA B-fragment order (float2).
// ---------------------------------------------------------------------------
__global__ __launch_bounds__(256)
void wsplit_kernel(const float* __restrict__ Wq,
                   const float* __restrict__ Wk,
                   const float* __restrict__ Wv) {
    int i    = blockIdx.x * 256 + threadIdx.x;
    int mat  = i >> 15;
    int rem  = i & 32767;
    int ksg  = rem >> 8;
    int j    = (rem >> 5) & 7;
    int lane = rem & 31;
    int g    = lane >> 2;
    int tig  = lane & 3;
    const float* W = (mat == 0) ? Wq : (mat == 1) ? Wk : Wv;
    int n = 8 * j + g;
    float w0 = W[(size_t)(8 * ksg + tig) * D_ + n];
    float w1 = W[(size_t)(8 * ksg + tig + 4) * D_ + n];
    g_Wfrag[i] = make_float2(f2tf32f(w0), f2tf32f(w1));
}

// ---------------------------------------------------------------------------
// Kernel 1: QKV projection, single-pass tf32 (xhi*whi).
// grid = (3, 256), mat fastest (X L2 reuse). BM=128, 256 threads.
// cp.async double-buffered, ONE barrier per k-chunk.
// ---------------------------------------------------------------------------
#define PBM 128
#define PKC 32
#define QKV_SMEM_BYTES (9216 * 4 + 2048 * 8)

__global__ __launch_bounds__(256)
void qkv_mma_kernel(const float* __restrict__ x) {
    extern __shared__ float dsm[];
    float*  Xs  = dsm;                          // [2][128][36]
    float2* WfS = (float2*)(dsm + 9216);        // [2][1024]

    const int mat = blockIdx.x;
    const float2* __restrict__ Wfg = g_Wfrag + mat * 32768;

    const int m0   = blockIdx.y * PBM;
    const int tid  = threadIdx.x;
    const int w    = tid >> 5;
    const int lane = tid & 31;
    const int g    = lane >> 2;
    const int tig  = lane & 3;
    const int r0   = 16 * w + g;
    const int r1   = r0 + 8;

    const uint32_t xs_u = s2u(Xs);
    const uint32_t wf_u = s2u(WfS);

    auto issue_stage = [&](int s, int k0) {
#pragma unroll
        for (int it = 0; it < 4; it++) {
            int i  = tid + 256 * it;
            int r  = i >> 3;
            int c4 = i & 7;
            cp_async16(xs_u + (uint32_t)(s * 4608 + r * 36 + 4 * c4) * 4,
                       x + (size_t)(m0 + r) * C_ + k0 + 4 * c4);
        }
        const float4* src = reinterpret_cast<const float4*>(
            Wfg + (k0 >> 3) * 256);
#pragma unroll
        for (int it = 0; it < 2; it++) {
            int i = tid + 256 * it;
            cp_async16(wf_u + (uint32_t)(s * 8192 + i * 16), src + i);
        }
    };

    float acc[8][4];
#pragma unroll
    for (int j = 0; j < 8; j++)
#pragma unroll
        for (int e = 0; e < 4; e++) acc[j][e] = 0.0f;

    issue_stage(0, 0);
    CP_COMMIT();

    for (int it = 0; it < 32; it++) {
        const int s = it & 1;
        CP_WAIT0();                      // chunk `it` landed (flying since it-1)
        __syncthreads();                 // readers of buf s^1 done; buf s visible
        if (it + 1 < 32) {
            issue_stage(s ^ 1, PKC * (it + 1));
            CP_COMMIT();
        }

        const float*  Xb = Xs + s * 4608;
        const float2* Wb = WfS + s * 1024;
#pragma unroll
        for (int ks = 0; ks < 4; ks++) {
            const int kc = 8 * ks;
            unsigned ahi[4];
            ahi[0] = f2tf32(Xb[r0 * 36 + kc + tig]);
            ahi[1] = f2tf32(Xb[r1 * 36 + kc + tig]);
            ahi[2] = f2tf32(Xb[r0 * 36 + kc + tig + 4]);
            ahi[3] = f2tf32(Xb[r1 * 36 + kc + tig + 4]);
#pragma unroll
            for (int j = 0; j < 8; j++) {
                float2 wf = Wb[ks * 256 + j * 32 + lane];
                mma_tf32(acc[j], ahi,
                         __float_as_uint(wf.x), __float_as_uint(wf.y));
            }
        }
    }

    // ---- Epilogue ----
    if (mat == 0) {
        // Q: row-major, scaled by log2(e)/sqrt(C) (base-2 softmax), tf32-rounded
        const float sc = 1.4426950408889634f / 32.0f;
#pragma unroll
        for (int j = 0; j < 8; j++) {
            int c = 8 * j + 2 * tig;
            *reinterpret_cast<float2*>(&g_Q[(size_t)(m0 + r0) * D_ + c]) =
                make_float2(f2tf32f(acc[j][0] * sc), f2tf32f(acc[j][1] * sc));
            *reinterpret_cast<float2*>(&g_Q[(size_t)(m0 + r1) * D_ + c]) =
                make_float2(f2tf32f(acc[j][2] * sc), f2tf32f(acc[j][3] * sc));
        }
    } else if (mat == 1) {
        // K scatter into QK^T B-fragment order.
        const int tileG = (m0 >> 6) + (w >> 2);
        const int jn0   = 2 * (w & 3);
        const int jn1   = jn0 + 1;
        const int slot  = tig >> 1;
        const int tp0   = (2 * tig) & 3;
        const int tp1   = tp0 + 1;
#pragma unroll
        for (int j = 0; j < 8; j++) {
            size_t base = ((size_t)(tileG * 8 + j) * 8);
            size_t b0i  = ((base + jn0) * 32 + 4 * g) * 2 + slot;
            size_t b1i  = ((base + jn1) * 32 + 4 * g) * 2 + slot;
            g_K[b0i + 2 * tp0] = f2tf32f(acc[j][0]);
            g_K[b0i + 2 * tp1] = f2tf32f(acc[j][1]);
            g_K[b1i + 2 * tp0] = f2tf32f(acc[j][2]);
            g_K[b1i + 2 * tp1] = f2tf32f(acc[j][3]);
        }
    } else {
        // V scatter into PV B-fragment order.
        const int tileG = (m0 >> 6) + (w >> 2);
        const int rks0  = 2 * (w & 3);
        const int rks1  = rks0 + 1;
        const int slot  = g >> 2;
        const int tigv  = g & 3;
#pragma unroll
        for (int j = 0; j < 8; j++) {
            size_t base0 = ((size_t)(tileG * 8 + rks0) * 8 + j) * 64;
            size_t base1 = ((size_t)(tileG * 8 + rks1) * 8 + j) * 64;
            int gv0 = 2 * tig, gv1 = 2 * tig + 1;
            g_V[base0 + (4 * gv0 + tigv) * 2 + slot] = f2tf32f(acc[j][0]);
            g_V[base0 + (4 * gv1 + tigv) * 2 + slot] = f2tf32f(acc[j][1]);
            g_V[base1 + (4 * gv0 + tigv) * 2 + slot] = f2tf32f(acc[j][2]);
            g_V[base1 + (4 * gv1 + tigv) * 2 + slot] = f2tf32f(acc[j][3]);
        }
    }
}

// ---------------------------------------------------------------------------
// Kernel 2: split-KV partial causal attention. grid (80, 16), 128 threads.
// K AND V double-buffered (one commit group, one tile ahead): per tile ONE
// wait_group 0 + ONE __syncthreads, zero mid-tile waits.
// NO Ps buffer: Q fragments via direct LDG; P C->A fragment conversion via
// quad shuffles (owner lane (lane&~3)|(tig>>1), +2 for the +4 column).
// Dynamic smem: K[2][2048]f2 + V[2][2048]f2 = 64 KB -> 3 blocks/SM.
// ---------------------------------------------------------------------------
#define ATT_SMEM_BYTES (16384 * 4)

__global__ __launch_bounds__(128, 3)
void attn_part_kernel() {
    extern __shared__ float dsm[];
    float2* Ksf = reinterpret_cast<float2*>(dsm);           // [2][2048] float2
    float2* Vsf = reinterpret_cast<float2*>(dsm + 8192);    // [2][2048] float2

    // Map work id -> (qt, chunk), qt descending so heavy chunks launch first.
    int qt = 0, ch = 0;
    {
        int wid = blockIdx.x;
        int acc = 0;
#pragma unroll
        for (int q = 31; q >= 0; q--) {
            int nc = (q >> 3) + 1;
            if (wid < acc + nc) { qt = q; ch = wid - acc; break; }
            acc += nc;
        }
    }
    const int b   = blockIdx.y;
    const int q0  = qt * 64;
    const int jt0 = ch * 8;
    const int jt1 = min(jt0 + 8, qt + 1);

    const int tid  = threadIdx.x;
    const int lane = tid & 31;
    const int g    = lane >> 2;
    const int tig  = lane & 3;
    const int r0   = 16 * (tid >> 5) + g;
    const int r1   = r0 + 8;

    const uint32_t k_u = s2u(Ksf);
    const uint32_t v_u = s2u(Vsf);

    // Issue K(jt)+V(jt) into buffer s (offsets in float4 units * 16 bytes).
    auto issue_kv = [&](int s, int jt) {
        const float4* Kg = reinterpret_cast<const float4*>(g_K)
                         + (size_t)(b * (T_ / 64) + jt) * 1024;
        const float4* Vg = reinterpret_cast<const float4*>(g_V)
                         + (size_t)(b * (T_ / 64) + jt) * 1024;
#pragma unroll
        for (int it = 0; it < 8; it++) {
            int i = tid + 128 * it;
            cp_async16(k_u + (uint32_t)(s * 1024 + i) * 16, Kg + i);
            cp_async16(v_u + (uint32_t)(s * 1024 + i) * 16, Vg + i);
        }
    };

    issue_kv(0, jt0);
    CP_COMMIT();

    // Q fragments directly from gmem (g_Q is L2-resident, read once per block)
    unsigned qf[8][4];
    {
        const float* Qg = g_Q + ((size_t)b * T_ + q0) * D_;
#pragma unroll
        for (int ks = 0; ks < 8; ks++) {
            const int kc = 8 * ks;
            qf[ks][0] = __float_as_uint(Qg[(size_t)r0 * D_ + kc + tig]);
            qf[ks][1] = __float_as_uint(Qg[(size_t)r1 * D_ + kc + tig]);
            qf[ks][2] = __float_as_uint(Qg[(size_t)r0 * D_ + kc + tig + 4]);
            qf[ks][3] = __float_as_uint(Qg[(size_t)r1 * D_ + kc + tig + 4]);
        }
    }

    float oacc[8][4];
#pragma unroll
    for (int j = 0; j < 8; j++)
#pragma unroll
        for (int e = 0; e < 4; e++) oacc[j][e] = 0.0f;
    float lr[2] = {0.0f, 0.0f};

    for (int jt = jt0; jt < jt1; jt++) {
        const int s = (jt - jt0) & 1;

        CP_WAIT0();       // KV(jt) landed (committed one full tile ago)
        __syncthreads();  // tile jt-1 readers of buf s^1 done; KV(jt) visible

        if (jt + 1 < jt1) {
            issue_kv(s ^ 1, jt + 1);
            CP_COMMIT();
        }

        // S = Q @ K^T on K buffer s (buffer stride 2048 float2)
        const float2* Kt = Ksf + s * 2048;
        float sacc[8][4];
#pragma unroll
        for (int j = 0; j < 8; j++)
#pragma unroll
            for (int e = 0; e < 4; e++) sacc[j][e] = 0.0f;
#pragma unroll
        for (int ks = 0; ks < 8; ks++) {
#pragma unroll
            for (int j = 0; j < 8; j++) {
                float2 kf = Kt[(ks * 8 + j) * 32 + lane];
                mma_tf32(sacc[j], qf[ks],
                         __float_as_uint(kf.x), __float_as_uint(kf.y));
            }
        }

        // Causal mask on the diagonal tile only
        if (jt == qt) {
#pragma unroll
            for (int j = 0; j < 8; j++) {
                int c = 8 * j + 2 * tig;
                if (c     > r0) sacc[j][0] = -CUDART_INF_F;
                if (c + 1 > r0) sacc[j][1] = -CUDART_INF_F;
                if (c     > r1) sacc[j][2] = -CUDART_INF_F;
                if (c + 1 > r1) sacc[j][3] = -CUDART_INF_F;
            }
        }

        // Fixed-max base-2 softmax: p = exp2(s); row sums via 2 quad shfls.
        // l sums use unrounded p; sacc is then overwritten with tf32-rounded
        // p (identical values to the old smem path).
#pragma unroll
        for (int r = 0; r < 2; r++) {
            const int e0 = 2 * r, e1 = 2 * r + 1;
            float sum = 0.0f;
#pragma unroll
            for (int j = 0; j < 8; j++) {
                float p0 = exp2f(sacc[j][e0]);
                float p1 = exp2f(sacc[j][e1]);
                sacc[j][e0] = f2tf32f(p0);
                sacc[j][e1] = f2tf32f(p1);
                sum += p0 + p1;
            }
            sum += __shfl_xor_sync(0xffffffffu, sum, 1);
            sum += __shfl_xor_sync(0xffffffffu, sum, 2);
            lr[r] += sum;
        }

        // O += P @ V on V buffer s. P A-fragments gathered from the quad via
        // shuffles: col 8ks+tig owner = lane (lane&~3)|(tig>>1), element
        // parity tig&1; col 8ks+tig+4 owner = +2.
        const float2* Vt = Vsf + s * 2048;
        const int slo = (lane & ~3) | (tig >> 1);
        const int shi = slo + 2;
        const bool odd = (tig & 1) != 0;
#pragma unroll
        for (int ks = 0; ks < 8; ks++) {
            float a0 = __shfl_sync(0xffffffffu, sacc[ks][0], slo);
            float a1 = __shfl_sync(0xffffffffu, sacc[ks][1], slo);
            float b0 = __shfl_sync(0xffffffffu, sacc[ks][2], slo);
            float b1 = __shfl_sync(0xffffffffu, sacc[ks][3], slo);
            float c0 = __shfl_sync(0xffffffffu, sacc[ks][0], shi);
            float c1 = __shfl_sync(0xffffffffu, sacc[ks][1], shi);
            float d0 = __shfl_sync(0xffffffffu, sacc[ks][2], shi);
            float d1 = __shfl_sync(0xffffffffu, sacc[ks][3], shi);
            unsigned pa[4];
            pa[0] = __float_as_uint(odd ? a1 : a0);
            pa[1] = __float_as_uint(odd ? b1 : b0);
            pa[2] = __float_as_uint(odd ? c1 : c0);
            pa[3] = __float_as_uint(odd ? d1 : d0);
#pragma unroll
            for (int j = 0; j < 8; j++) {
                float2 vf = Vt[(ks * 8 + j) * 32 + lane];
                mma_tf32(oacc[j], pa,
                         __float_as_uint(vf.x), __float_as_uint(vf.y));
            }
        }
    }

    // Store unnormalized partial O and l for this chunk
    float* Op = g_Opart[ch] + ((size_t)b * T_ + q0) * D_;
#pragma unroll
    for (int j = 0; j < 8; j++) {
        int c = 8 * j + 2 * tig;
        *reinterpret_cast<float2*>(&Op[(size_t)r0 * D_ + c]) =
            make_float2(oacc[j][0], oacc[j][1]);
        *reinterpret_cast<float2*>(&Op[(size_t)r1 * D_ + c]) =
            make_float2(oacc[j][2], oacc[j][3]);
    }
    if (tig == 0) {
        g_Lpart[ch][(size_t)b * T_ + q0 + r0] = lr[0];
        g_Lpart[ch][(size_t)b * T_ + q0 + r1] = lr[1];
    }
}

// ---------------------------------------------------------------------------
// Kernel 3: combine partials and normalize. One thread per float4 of output.
// ---------------------------------------------------------------------------
__global__ __launch_bounds__(256)
void norm_kernel(float* __restrict__ out) {
    int idx = blockIdx.x * 256 + threadIdx.x;     // 0 .. 524287
    int d4  = idx & 15;
    int t   = (idx >> 4) & (T_ - 1);
    int b   = idx >> 15;
    int nc  = ((t >> 6) >> 3) + 1;                // chunks for this q-tile

    size_t row = (size_t)b * T_ + t;
    float4 o = make_float4(0.f, 0.f, 0.f, 0.f);
    float  l = 0.f;
#pragma unroll 4
    for (int c = 0; c < nc; c++) {
        float4 p = *reinterpret_cast<const float4*>(
            &g_Opart[c][row * D_ + 4 * d4]);
        o.x += p.x; o.y += p.y; o.z += p.z; o.w += p.w;
        l += g_Lpart[c][row];
    }
    float inv = 1.0f / l;
    *reinterpret_cast<float4*>(&out[row * D_ + 4 * d4]) =
        make_float4(o.x * inv, o.y * inv, o.z * inv, o.w * inv);
}

// ---------------------------------------------------------------------------
extern "C" void kernel_launch(void* const* d_in, const int* in_sizes, int n_in,
                              void* d_out, int out_size) {
    const float* x  = (const float*)d_in[0];
    const float* Wq = (const float*)d_in[1];
    const float* Wk = (const float*)d_in[2];
    const float* Wv = (const float*)d_in[3];
    float* out = (float*)d_out;

    cudaFuncSetAttribute(qkv_mma_kernel,
                         cudaFuncAttributeMaxDynamicSharedMemorySize,
                         QKV_SMEM_BYTES);
    cudaFuncSetAttribute(attn_part_kernel,
                         cudaFuncAttributeMaxDynamicSharedMemorySize,
                         ATT_SMEM_BYTES);

    wsplit_kernel<<<384, 256>>>(Wq, Wk, Wv);
    qkv_mma_kernel<<<dim3(3, (B_ * T_) / PBM), 256, QKV_SMEM_BYTES>>>(x);
    attn_part_kernel<<<dim3(80, B_), 128, ATT_SMEM_BYTES>>>();
    norm_kernel<<<(B_ * T_ * D_ / 4) / 256, 256>>>(out);
}